// round 12
// baseline (speedup 1.0000x reference)
#include <cuda_runtime.h>
#include <math.h>

// Problem constants
#define BB 256      // batch
#define RR 1152     // routes
#define CC 10       // caps
#define DD 16       // d_out
#define II 8        // d_in
#define NN 160      // CC*DD

// GEMM tiling
#define BT 64            // batch tile per block
#define RCHUNK 16        // routes per block (K split)
#define NKB 72           // RR / RCHUNK
#define NBT 4            // BB / BT
#define NSTAGE (RCHUNK/4)
#define GT 256           // gemm threads

#define BTB 8            // batch tile in t_kernel

typedef unsigned long long u64;

// Scratch (static device arrays; no allocation anywhere)
__device__ float g_wsumT[CC * II * RR];       // [c][i][r] sum_d W[r,c,d,i]
__device__ float g_t[CC * BB * RR];           // t[c][b][r] = sum_d u_hat
__device__ float g_spart[NKB * BB * NN];      // per-K-chunk partial s (11.8 MB)
__device__ float g_v[BB * NN];                // squashed v
__device__ float g_bT[NN * RR];               // routing logits, transposed [n][r]
__device__ float g_c[RR * NN];                // softmax(b) over r, [r][n]

// ---- packed f32x2 helpers (FFMA2 path on sm_103a) ----
__device__ __forceinline__ u64 pack2(float lo, float hi) {
    u64 r;
    asm("mov.b64 %0, {%1, %2};" : "=l"(r) : "f"(lo), "f"(hi));
    return r;
}
__device__ __forceinline__ float lo2(u64 v) { return __uint_as_float((unsigned int)v); }
__device__ __forceinline__ float hi2(u64 v) { return __uint_as_float((unsigned int)(v >> 32)); }
__device__ __forceinline__ void fma2(u64& d, u64 a, u64 b) {
    asm("fma.rn.f32x2 %0, %1, %2, %0;" : "+l"(d) : "l"(a), "l"(b));
}

// ---------------------------------------------------------------------------
// wsumT[c][i][r] = sum_d W[r,c,d,i]
// ---------------------------------------------------------------------------
__global__ void wsum_kernel(const float* __restrict__ W) {
    int id = blockIdx.x * blockDim.x + threadIdx.x;   // over RR*CC*II
    if (id >= RR * CC * II) return;
    int rc = id / II, i = id - rc * II;
    int r = rc / CC, c = rc - r * CC;
    const float* p = W + rc * DD * II + i;
    float s = 0.f;
    #pragma unroll
    for (int d = 0; d < DD; d++) s += p[d * II];
    g_wsumT[(c * II + i) * RR + r] = s;
}

// ---------------------------------------------------------------------------
// t[c][b][r] = sum_i wsumT[c][i][r] * u[b,r,i]   (iteration-invariant)
// ---------------------------------------------------------------------------
__global__ __launch_bounds__(128) void t_kernel(const float* __restrict__ u) {
    const int r = blockIdx.x * 128 + threadIdx.x;
    const int b0 = blockIdx.y * BTB;

    float uu[BTB][II];
    #pragma unroll
    for (int bi = 0; bi < BTB; bi++) {
        const float4* up = (const float4*)(u + ((b0 + bi) * RR + r) * II);
        float4 a = up[0], b = up[1];
        uu[bi][0] = a.x; uu[bi][1] = a.y; uu[bi][2] = a.z; uu[bi][3] = a.w;
        uu[bi][4] = b.x; uu[bi][5] = b.y; uu[bi][6] = b.z; uu[bi][7] = b.w;
    }

    #pragma unroll
    for (int c = 0; c < CC; c++) {
        float ws[II];
        #pragma unroll
        for (int i = 0; i < II; i++) ws[i] = g_wsumT[(c * II + i) * RR + r];
        #pragma unroll
        for (int bi = 0; bi < BTB; bi++) {
            float s = 0.f;
            #pragma unroll
            for (int i = 0; i < II; i++) s += ws[i] * uu[bi][i];
            g_t[(c * BB + b0 + bi) * RR + r] = s;
        }
    }
}

// ---------------------------------------------------------------------------
// s_part[kb][b][n] = sum_{r in chunk kb} c[r,n] * sum_i W[r,n,i]*u[b,r,i]
// 256 threads, 8b x 5n per thread. __launch_bounds__(256,2): 2 blocks/SM
// (grid 288), staging LDG latency hidden by the co-resident block.
// Double-buffered smem, ONE __syncthreads per stage, 4 stages.
// ---------------------------------------------------------------------------
__global__ __launch_bounds__(GT, 2) void gemm_kernel(
    const float* __restrict__ u, const float* __restrict__ W,
    int use_c, float cuni)
{
    __shared__ u64 u_s[2][4][BT][4];   // [buf][rs][m][ip]  16 KB
    __shared__ u64 w_s[2][4][4][NN];   // [buf][rs][ip][n]  40 KB

    const int tid = threadIdx.x;
    const int tx = tid & 31, ty = tid >> 5;   // ty 0..7
    const int bt = blockIdx.x, kb = blockIdx.y;
    const int r0 = kb * RCHUNK;

    const u64 z = pack2(0.f, 0.f);
    u64 acc[8][5];
    #pragma unroll
    for (int jm = 0; jm < 8; jm++)
        #pragma unroll
        for (int jn = 0; jn < 5; jn++) acc[jm][jn] = z;

    // ---- staging decomposition (stage-invariant) ----
    // u tile: thread owns row (srs, sbl): 8 consecutive floats
    const int sbl = tid & 63;          // b within tile
    const int srs = (tid >> 6) & 3;    // r within 4-row stage
    const float* ubase = u + ((bt * BT + sbl) * RR + r0 + srs) * II;

    // W tile: 1280 float4; thread handles idx = tid + 256k, k<5 (exact)
    int wo[5], wiq[5], wrs[5], wn[5];
    #pragma unroll
    for (int k = 0; k < 5; k++) {
        int idx = tid + GT * k;          // 0..1279
        wrs[k] = idx / 320;
        int rem = idx - wrs[k] * 320;
        wn[k] = rem >> 1;
        wiq[k] = rem & 1;
        wo[k] = (r0 + wrs[k]) * NN + wn[k];
    }

    #pragma unroll
    for (int st = 0; st < NSTAGE; st++) {
        const int buf = st & 1;

        // ---- stage: load (all LDGs issued up front), scale, store to smem ----
        {
            const float* ub = ubase + st * (4 * II);
            float4 au0 = *(const float4*)(ub);
            float4 au1 = *(const float4*)(ub + 4);
            float4 aw[5];
            float  ac[5];
            #pragma unroll
            for (int k = 0; k < 5; k++) {
                int o = wo[k] + st * (4 * NN);
                ac[k] = use_c ? g_c[o] : cuni;
                aw[k] = *(const float4*)(W + o * 8 + wiq[k] * 4);
            }
            *(float4*)&u_s[buf][srs][sbl][0] = au0;
            *(float4*)&u_s[buf][srs][sbl][2] = au1;
            #pragma unroll
            for (int k = 0; k < 5; k++) {
                w_s[buf][wrs[k]][wiq[k] * 2 + 0][wn[k]] = pack2(aw[k].x * ac[k], aw[k].y * ac[k]);
                w_s[buf][wrs[k]][wiq[k] * 2 + 1][wn[k]] = pack2(aw[k].z * ac[k], aw[k].w * ac[k]);
            }
        }
        __syncthreads();   // buf ready; also orders compute(st-2) before this commit

        // ---- compute on current buffer: 8b x 5n per thread ----
        #pragma unroll
        for (int rs = 0; rs < 4; rs++) {
            #pragma unroll
            for (int ip = 0; ip < 4; ip++) {
                u64 ww[5];
                #pragma unroll
                for (int jn = 0; jn < 5; jn++) ww[jn] = w_s[buf][rs][ip][tx + 32 * jn];
                #pragma unroll
                for (int jm = 0; jm < 8; jm++) {
                    u64 uv = u_s[buf][rs][ty * 8 + jm][ip];   // broadcast
                    #pragma unroll
                    for (int jn = 0; jn < 5; jn++)
                        fma2(acc[jm][jn], uv, ww[jn]);
                }
            }
        }
    }

    #pragma unroll
    for (int jm = 0; jm < 8; jm++) {
        int b = bt * BT + ty * 8 + jm;
        #pragma unroll
        for (int jn = 0; jn < 5; jn++) {
            int n = tx + 32 * jn;
            g_spart[(kb * BB + b) * NN + n] = lo2(acc[jm][jn]) + hi2(acc[jm][jn]);
        }
    }
}

// ---------------------------------------------------------------------------
// Reduce K-chunk partials (72), squash, write v (and final output).
// grid 320 x 128 threads, scalar; loads batched 12-wide for MLP.
// ---------------------------------------------------------------------------
__global__ __launch_bounds__(128) void reduce_squash_kernel(float* __restrict__ dout) {
    const int idx = blockIdx.x * 128 + threadIdx.x;   // over BB*NN = 40960
    const int stride = BB * NN;

    float s = 0.f;
    #pragma unroll
    for (int bat = 0; bat < NKB / 12; bat++) {
        float x[12];
        #pragma unroll
        for (int j = 0; j < 12; j++)
            x[j] = g_spart[(bat * 12 + j) * stride + idx];
        float a0 = 0.f, a1 = 0.f, a2 = 0.f, a3 = 0.f;
        #pragma unroll
        for (int j = 0; j < 12; j += 4) {
            a0 += x[j]; a1 += x[j + 1]; a2 += x[j + 2]; a3 += x[j + 3];
        }
        s += (a0 + a1) + (a2 + a3);
    }

    float sq = s * s;
    float o = sq / (1.f + sq) * s / (sqrtf(sq) + 1e-5f);
    g_v[idx] = o;
    dout[idx] = o;
}

// ---------------------------------------------------------------------------
// bT[c*16+d][r] += (1/B) sum_b t[c][b][r] * v[b, c*16+d]
// ---------------------------------------------------------------------------
__global__ __launch_bounds__(128) void update_kernel(int first) {
    __shared__ u64 v_s[BB][DD / 2];   // 16 KB
    const int c = blockIdx.y;
    const int r = blockIdx.x * 128 + threadIdx.x;

    #pragma unroll
    for (int k = 0; k < 8; k++) {
        int idx = threadIdx.x + 128 * k;   // 0..1023
        int b = idx >> 2, q = idx & 3;
        const float4 v4 = *(const float4*)(g_v + b * NN + c * DD + q * 4);
        v_s[b][q * 2 + 0] = pack2(v4.x, v4.y);
        v_s[b][q * 2 + 1] = pack2(v4.z, v4.w);
    }
    __syncthreads();

    const u64 z = pack2(0.f, 0.f);
    u64 acc[8];
    #pragma unroll
    for (int j = 0; j < 8; j++) acc[j] = z;

    const float* tp = g_t + (c * BB) * RR + r;
    for (int b0 = 0; b0 < BB; b0 += 8) {
        float tv[8];
        #pragma unroll
        for (int q = 0; q < 8; q++) tv[q] = tp[(b0 + q) * RR];
        #pragma unroll
        for (int q = 0; q < 8; q++) {
            u64 t2 = pack2(tv[q], tv[q]);
            #pragma unroll
            for (int j = 0; j < 8; j++) fma2(acc[j], t2, v_s[b0 + q][j]);
        }
    }

    const float inv = 1.f / (float)BB;
    #pragma unroll
    for (int j = 0; j < 8; j++) {
        float x = lo2(acc[j]) * inv;
        float y = hi2(acc[j]) * inv;
        int o0 = (c * DD + 2 * j) * RR + r;
        int o1 = (c * DD + 2 * j + 1) * RR + r;
        if (!first) { x += g_bT[o0]; y += g_bT[o1]; }
        g_bT[o0] = x;
        g_bT[o1] = y;
    }
}

// ---------------------------------------------------------------------------
// c[r,n] = softmax over r of bT[n][r].  grid NN blocks, 128 threads.
// ---------------------------------------------------------------------------
__global__ __launch_bounds__(128) void softmax_kernel() {
    __shared__ float red[128];
    const int n = blockIdx.x;
    const int tid = threadIdx.x;
    const float* bp = g_bT + n * RR;

    float vals[9];
    #pragma unroll
    for (int j = 0; j < 9; j++) vals[j] = bp[tid + 128 * j];

    float m = vals[0];
    #pragma unroll
    for (int j = 1; j < 9; j++) m = fmaxf(m, vals[j]);
    red[tid] = m;
    __syncthreads();
    for (int s = 64; s > 0; s >>= 1) {
        if (tid < s) red[tid] = fmaxf(red[tid], red[tid + s]);
        __syncthreads();
    }
    m = red[0];
    __syncthreads();

    float e[9];
    float lsum = 0.f;
    #pragma unroll
    for (int j = 0; j < 9; j++) { e[j] = expf(vals[j] - m); lsum += e[j]; }
    red[tid] = lsum;
    __syncthreads();
    for (int s = 64; s > 0; s >>= 1) {
        if (tid < s) red[tid] += red[tid + s];
        __syncthreads();
    }
    float inv = 1.f / red[0];

    #pragma unroll
    for (int j = 0; j < 9; j++)
        g_c[(tid + 128 * j) * NN + n] = e[j] * inv;
}

// ---------------------------------------------------------------------------
extern "C" void kernel_launch(void* const* d_in, const int* in_sizes, int n_in,
                              void* d_out, int out_size) {
    const float* u = (const float*)d_in[0];   // (B, R, 8)
    const float* W = (const float*)d_in[1];   // (R, C, 16, 8)
    float* out = (float*)d_out;               // (B, C, 16) = 40960 floats

    wsum_kernel<<<(RR * CC * II + 255) / 256, 256>>>(W);
    t_kernel<<<dim3(RR / 128, BB / BTB), 128>>>(u);

    // Iteration 0: c_ij uniform = 1/R
    gemm_kernel<<<dim3(NBT, NKB), GT>>>(u, W, 0, 1.0f / (float)RR);
    reduce_squash_kernel<<<320, 128>>>(out);
    update_kernel<<<dim3(RR / 128, CC), 128>>>(1);
    softmax_kernel<<<NN, 128>>>();

    // Iteration 1
    gemm_kernel<<<dim3(NBT, NKB), GT>>>(u, W, 1, 0.f);
    reduce_squash_kernel<<<320, 128>>>(out);
    update_kernel<<<dim3(RR / 128, CC), 128>>>(0);
    softmax_kernel<<<NN, 128>>>();

    // Iteration 2 (final v -> out)
    gemm_kernel<<<dim3(NBT, NKB), GT>>>(u, W, 1, 0.f);
    reduce_squash_kernel<<<320, 128>>>(out);
}

// round 13
// speedup vs baseline: 1.0629x; 1.0629x over previous
#include <cuda_runtime.h>
#include <math.h>

// Problem constants
#define BB 256      // batch
#define RR 1152     // routes
#define CC 10       // caps
#define DD 16       // d_out
#define II 8        // d_in
#define NN 160      // CC*DD

// GEMM tiling
#define BT 64            // batch tile per block
#define RCHUNK 32        // routes per block (K split)
#define NKB 36           // RR / RCHUNK
#define NBT 4            // BB / BT
#define NSTAGE (RCHUNK/4)
#define GT 256           // gemm threads

#define BTB 8            // batch tile in t_kernel

typedef unsigned long long u64;

// Scratch (static device arrays; no allocation anywhere)
__device__ float g_wsumT[CC * II * RR];       // [c][i][r] sum_d W[r,c,d,i]
__device__ float g_t[CC * BB * RR];           // t[c][b][r] = sum_d u_hat
__device__ float g_spart[NKB * BB * NN];      // per-K-chunk partial s
__device__ float g_v[BB * NN];                // squashed v
__device__ float g_bT[NN * RR];               // routing logits, transposed [n][r]
__device__ float g_c[RR * NN];                // softmax(b) over r, [r][n]

// ---- packed f32x2 helpers (FFMA2 path on sm_103a) ----
__device__ __forceinline__ u64 pack2(float lo, float hi) {
    u64 r;
    asm("mov.b64 %0, {%1, %2};" : "=l"(r) : "f"(lo), "f"(hi));
    return r;
}
__device__ __forceinline__ float lo2(u64 v) { return __uint_as_float((unsigned int)v); }
__device__ __forceinline__ float hi2(u64 v) { return __uint_as_float((unsigned int)(v >> 32)); }
__device__ __forceinline__ void fma2(u64& d, u64 a, u64 b) {
    asm("fma.rn.f32x2 %0, %1, %2, %0;" : "+l"(d) : "l"(a), "l"(b));
}

// ---------------------------------------------------------------------------
// wsumT[c][i][r] = sum_d W[r,c,d,i]
// ---------------------------------------------------------------------------
__global__ void wsum_kernel(const float* __restrict__ W) {
    int id = blockIdx.x * blockDim.x + threadIdx.x;   // over RR*CC*II
    if (id >= RR * CC * II) return;
    int rc = id / II, i = id - rc * II;
    int r = rc / CC, c = rc - r * CC;
    const float* p = W + rc * DD * II + i;
    float s = 0.f;
    #pragma unroll
    for (int d = 0; d < DD; d++) s += p[d * II];
    g_wsumT[(c * II + i) * RR + r] = s;
}

// ---------------------------------------------------------------------------
// t[c][b][r] = sum_i wsumT[c][i][r] * u[b,r,i]   (iteration-invariant)
// ---------------------------------------------------------------------------
__global__ __launch_bounds__(128) void t_kernel(const float* __restrict__ u) {
    const int r = blockIdx.x * 128 + threadIdx.x;
    const int b0 = blockIdx.y * BTB;

    float uu[BTB][II];
    #pragma unroll
    for (int bi = 0; bi < BTB; bi++) {
        const float4* up = (const float4*)(u + ((b0 + bi) * RR + r) * II);
        float4 a = up[0], b = up[1];
        uu[bi][0] = a.x; uu[bi][1] = a.y; uu[bi][2] = a.z; uu[bi][3] = a.w;
        uu[bi][4] = b.x; uu[bi][5] = b.y; uu[bi][6] = b.z; uu[bi][7] = b.w;
    }

    #pragma unroll
    for (int c = 0; c < CC; c++) {
        float ws[II];
        #pragma unroll
        for (int i = 0; i < II; i++) ws[i] = g_wsumT[(c * II + i) * RR + r];
        #pragma unroll
        for (int bi = 0; bi < BTB; bi++) {
            float s = 0.f;
            #pragma unroll
            for (int i = 0; i < II; i++) s += ws[i] * uu[bi][i];
            g_t[(c * BB + b0 + bi) * RR + r] = s;
        }
    }
}

// ---------------------------------------------------------------------------
// s_part[kb][b][n] = sum_{r in chunk kb} c[r,n] * sum_i W[r,n,i]*u[b,r,i]
// 256 threads; thread (ty 0..7, tx 0..31): 8 b's x 5 n's.
// w_s holds 16B entries [rs][iq][n] so inner W reads are LDS.128,
// contiguous 16B/lane (conflict-free); u reads are LDS.128 broadcasts.
// Register-prefetch double buffering, ONE __syncthreads per stage.
// ---------------------------------------------------------------------------
__global__ __launch_bounds__(GT, 1) void gemm_kernel(
    const float* __restrict__ u, const float* __restrict__ W,
    int use_c, float cuni)
{
    __shared__ u64 u_s[2][4][BT][4];          // [buf][rs][m][ip]   16 KB
    __shared__ ulonglong2 w_s[2][4][2][NN];   // [buf][rs][iq][n]   40 KB

    const int tid = threadIdx.x;
    const int tx = tid & 31, ty = tid >> 5;   // ty 0..7
    const int bt = blockIdx.x, kb = blockIdx.y;
    const int r0 = kb * RCHUNK;

    const u64 z = pack2(0.f, 0.f);
    u64 acc[8][5];
    #pragma unroll
    for (int jm = 0; jm < 8; jm++)
        #pragma unroll
        for (int jn = 0; jn < 5; jn++) acc[jm][jn] = z;

    // ---- staging decomposition (stage-invariant) ----
    const int sbl = tid & 63;          // b within tile
    const int srs = (tid >> 6) & 3;    // r within 4-row stage
    const float* ubase = u + ((bt * BT + sbl) * RR + r0 + srs) * II;

    int wo[5], wiq[5], wrs[5], wn[5];
    #pragma unroll
    for (int k = 0; k < 5; k++) {
        int idx = tid + GT * k;          // 0..1279
        wrs[k] = idx / 320;
        int rem = idx - wrs[k] * 320;
        wn[k] = rem >> 1;
        wiq[k] = rem & 1;
        wo[k] = (r0 + wrs[k]) * NN + wn[k];
    }

    // prefetch registers
    float4 pu0, pu1;
    float4 pw[5];
    float  pc[5];

    // prologue: prefetch stage 0
    {
        pu0 = *(const float4*)(ubase);
        pu1 = *(const float4*)(ubase + 4);
        #pragma unroll
        for (int k = 0; k < 5; k++) {
            pc[k] = use_c ? g_c[wo[k]] : cuni;
            pw[k] = *(const float4*)(W + wo[k] * 8 + wiq[k] * 4);
        }
    }

    #pragma unroll 2
    for (int st = 0; st < NSTAGE; st++) {
        const int buf = st & 1;

        // commit prefetched tile to smem (fold c into W) — 128-bit stores
        *(float4*)&u_s[buf][srs][sbl][0] = pu0;
        *(float4*)&u_s[buf][srs][sbl][2] = pu1;
        #pragma unroll
        for (int k = 0; k < 5; k++) {
            float4 wv = make_float4(pw[k].x * pc[k], pw[k].y * pc[k],
                                    pw[k].z * pc[k], pw[k].w * pc[k]);
            *(float4*)&w_s[buf][wrs[k]][wiq[k]][wn[k]] = wv;
        }
        __syncthreads();   // buf visible; also guards next commit to other buf

        // prefetch next stage (lands in the other buffer next iter)
        if (st < NSTAGE - 1) {
            const float* ub = ubase + (st + 1) * (4 * II);
            pu0 = *(const float4*)(ub);
            pu1 = *(const float4*)(ub + 4);
            #pragma unroll
            for (int k = 0; k < 5; k++) {
                int o = wo[k] + (st + 1) * (4 * NN);
                pc[k] = use_c ? g_c[o] : cuni;
                pw[k] = *(const float4*)(W + o * 8 + wiq[k] * 4);
            }
        }

        // compute on current buffer: 8b x 5n per thread, LDS.128 everywhere
        #pragma unroll
        for (int rs = 0; rs < 4; rs++) {
            #pragma unroll
            for (int ipp = 0; ipp < 2; ipp++) {
                ulonglong2 ww[5];
                #pragma unroll
                for (int jn = 0; jn < 5; jn++)
                    ww[jn] = w_s[buf][rs][ipp][tx + 32 * jn];
                #pragma unroll
                for (int jm = 0; jm < 8; jm++) {
                    ulonglong2 uv = *(const ulonglong2*)&u_s[buf][rs][ty * 8 + jm][ipp * 2];
                    #pragma unroll
                    for (int jn = 0; jn < 5; jn++) {
                        fma2(acc[jm][jn], uv.x, ww[jn].x);
                        fma2(acc[jm][jn], uv.y, ww[jn].y);
                    }
                }
            }
        }
    }

    #pragma unroll
    for (int jm = 0; jm < 8; jm++) {
        int b = bt * BT + ty * 8 + jm;
        #pragma unroll
        for (int jn = 0; jn < 5; jn++) {
            int n = tx + 32 * jn;
            g_spart[(kb * BB + b) * NN + n] = lo2(acc[jm][jn]) + hi2(acc[jm][jn]);
        }
    }
}

// ---------------------------------------------------------------------------
// Reduce K-chunk partials (36), squash, write v (and final output).
// grid 320 x 128 threads, scalar; loads batched 12-wide for MLP.
// ---------------------------------------------------------------------------
__global__ __launch_bounds__(128) void reduce_squash_kernel(float* __restrict__ dout) {
    const int idx = blockIdx.x * 128 + threadIdx.x;   // over BB*NN = 40960
    const int stride = BB * NN;

    float s = 0.f;
    #pragma unroll
    for (int bat = 0; bat < NKB / 12; bat++) {
        float x[12];
        #pragma unroll
        for (int j = 0; j < 12; j++)
            x[j] = g_spart[(bat * 12 + j) * stride + idx];
        float a0 = 0.f, a1 = 0.f, a2 = 0.f, a3 = 0.f;
        #pragma unroll
        for (int j = 0; j < 12; j += 4) {
            a0 += x[j]; a1 += x[j + 1]; a2 += x[j + 2]; a3 += x[j + 3];
        }
        s += (a0 + a1) + (a2 + a3);
    }

    float sq = s * s;
    float o = sq / (1.f + sq) * s / (sqrtf(sq) + 1e-5f);
    g_v[idx] = o;
    dout[idx] = o;
}

// ---------------------------------------------------------------------------
// bT[c*16+d][r] += (1/B) sum_b t[c][b][r] * v[b, c*16+d]
// ---------------------------------------------------------------------------
__global__ __launch_bounds__(128) void update_kernel(int first) {
    __shared__ u64 v_s[BB][DD / 2];   // 16 KB
    const int c = blockIdx.y;
    const int r = blockIdx.x * 128 + threadIdx.x;

    #pragma unroll
    for (int k = 0; k < 8; k++) {
        int idx = threadIdx.x + 128 * k;   // 0..1023
        int b = idx >> 2, q = idx & 3;
        const float4 v4 = *(const float4*)(g_v + b * NN + c * DD + q * 4);
        v_s[b][q * 2 + 0] = pack2(v4.x, v4.y);
        v_s[b][q * 2 + 1] = pack2(v4.z, v4.w);
    }
    __syncthreads();

    const u64 z = pack2(0.f, 0.f);
    u64 acc[8];
    #pragma unroll
    for (int j = 0; j < 8; j++) acc[j] = z;

    const float* tp = g_t + (c * BB) * RR + r;
    for (int b0 = 0; b0 < BB; b0 += 8) {
        float tv[8];
        #pragma unroll
        for (int q = 0; q < 8; q++) tv[q] = tp[(b0 + q) * RR];
        #pragma unroll
        for (int q = 0; q < 8; q++) {
            u64 t2 = pack2(tv[q], tv[q]);
            #pragma unroll
            for (int j = 0; j < 8; j++) fma2(acc[j], t2, v_s[b0 + q][j]);
        }
    }

    const float inv = 1.f / (float)BB;
    #pragma unroll
    for (int j = 0; j < 8; j++) {
        float x = lo2(acc[j]) * inv;
        float y = hi2(acc[j]) * inv;
        int o0 = (c * DD + 2 * j) * RR + r;
        int o1 = (c * DD + 2 * j + 1) * RR + r;
        if (!first) { x += g_bT[o0]; y += g_bT[o1]; }
        g_bT[o0] = x;
        g_bT[o1] = y;
    }
}

// ---------------------------------------------------------------------------
// c[r,n] = softmax over r of bT[n][r].  grid NN blocks, 128 threads.
// ---------------------------------------------------------------------------
__global__ __launch_bounds__(128) void softmax_kernel() {
    __shared__ float red[128];
    const int n = blockIdx.x;
    const int tid = threadIdx.x;
    const float* bp = g_bT + n * RR;

    float vals[9];
    #pragma unroll
    for (int j = 0; j < 9; j++) vals[j] = bp[tid + 128 * j];

    float m = vals[0];
    #pragma unroll
    for (int j = 1; j < 9; j++) m = fmaxf(m, vals[j]);
    red[tid] = m;
    __syncthreads();
    for (int s = 64; s > 0; s >>= 1) {
        if (tid < s) red[tid] = fmaxf(red[tid], red[tid + s]);
        __syncthreads();
    }
    m = red[0];
    __syncthreads();

    float e[9];
    float lsum = 0.f;
    #pragma unroll
    for (int j = 0; j < 9; j++) { e[j] = expf(vals[j] - m); lsum += e[j]; }
    red[tid] = lsum;
    __syncthreads();
    for (int s = 64; s > 0; s >>= 1) {
        if (tid < s) red[tid] += red[tid + s];
        __syncthreads();
    }
    float inv = 1.f / red[0];

    #pragma unroll
    for (int j = 0; j < 9; j++)
        g_c[(tid + 128 * j) * NN + n] = e[j] * inv;
}

// ---------------------------------------------------------------------------
extern "C" void kernel_launch(void* const* d_in, const int* in_sizes, int n_in,
                              void* d_out, int out_size) {
    const float* u = (const float*)d_in[0];   // (B, R, 8)
    const float* W = (const float*)d_in[1];   // (R, C, 16, 8)
    float* out = (float*)d_out;               // (B, C, 16) = 40960 floats

    wsum_kernel<<<(RR * CC * II + 255) / 256, 256>>>(W);
    t_kernel<<<dim3(RR / 128, BB / BTB), 128>>>(u);

    // Iteration 0: c_ij uniform = 1/R
    gemm_kernel<<<dim3(NBT, NKB), GT>>>(u, W, 0, 1.0f / (float)RR);
    reduce_squash_kernel<<<320, 128>>>(out);
    update_kernel<<<dim3(RR / 128, CC), 128>>>(1);
    softmax_kernel<<<NN, 128>>>();

    // Iteration 1
    gemm_kernel<<<dim3(NBT, NKB), GT>>>(u, W, 1, 0.f);
    reduce_squash_kernel<<<320, 128>>>(out);
    update_kernel<<<dim3(RR / 128, CC), 128>>>(0);
    softmax_kernel<<<NN, 128>>>();

    // Iteration 2 (final v -> out)
    gemm_kernel<<<dim3(NBT, NKB), GT>>>(u, W, 1, 0.f);
    reduce_squash_kernel<<<320, 128>>>(out);
}

// round 16
// speedup vs baseline: 1.3476x; 1.2678x over previous
#include <cuda_runtime.h>
#include <math.h>
#include <cstdint>

// Problem constants
#define BB 256      // batch
#define RR 1152     // routes
#define CC 10       // caps
#define DD 16       // d_out
#define II 8        // d_in
#define NN 160      // CC*DD

// GEMM tiling
#define RCHUNK 32                // routes per K-chunk (K = 256)
#define NKB 36                   // RR / RCHUNK
#define MT 64                    // batch rows per CTA
#define NBT 4                    // BB / MT
#define NSTAGE 8                 // RCHUNK/4 (stage = 4 routes = K32)

#define BTB 8                    // batch tile in t_kernel

typedef unsigned long long u64;

// Scratch (static device arrays; no allocation anywhere)
__device__ float g_wsumT[CC * II * RR];       // [c][i][r] sum_d W[r,c,d,i]
__device__ float g_t[CC * BB * RR];           // t[c][b][r]
__device__ float g_spart[NKB * BB * NN];      // per-K-chunk partial s (5.9 MB)
__device__ float g_v[BB * NN];                // squashed v
__device__ float g_bT[NN * RR];               // routing logits, transposed [n][r]
__device__ float g_c[RR * NN];                // softmax(b) over r, [r][n]

// ---- helpers ----
__device__ __forceinline__ u64 pack2(float lo, float hi) {
    u64 r;
    asm("mov.b64 %0, {%1, %2};" : "=l"(r) : "f"(lo), "f"(hi));
    return r;
}
__device__ __forceinline__ float lo2(u64 v) { return __uint_as_float((unsigned int)v); }
__device__ __forceinline__ float hi2(u64 v) { return __uint_as_float((unsigned int)(v >> 32)); }
__device__ __forceinline__ void fma2(u64& d, u64 a, u64 b) {
    asm("fma.rn.f32x2 %0, %1, %2, %0;" : "+l"(d) : "l"(a), "l"(b));
}
__device__ __forceinline__ uint32_t f2tf32(float x) {
    uint32_t r;
    asm("cvt.rna.tf32.f32 %0, %1;" : "=r"(r) : "f"(x));
    return r;
}

// smem word layouts (uint32 units)
// A fragments: [buf][mg][kt][lane][slot], slot = {a0,a2,a1,a3}; rr-stride padded 132
#define A_WORD(buf, mg, rr, lane, slot) \
    (((((buf) * 4 + (mg)) * 4 + (rr)) * 132) + (lane) * 4 + (slot))
#define A_WORDS 4224
// B fragments: [buf][nh][nt][kt] block of 64 words (+4 pad); word = bg*8 + tB*2 + reg
#define B_BASE(buf, nh, nt, rr) \
    ((((((buf) * 2 + (nh)) * 10 + (nt)) * 4) + (rr)) * 68)
#define B_WORDS 10880
#define SMEM_TOTAL ((A_WORDS + B_WORDS) * 4)   // 60416 bytes

// ---------------------------------------------------------------------------
// wsumT[c][i][r] = sum_d W[r,c,d,i]
// ---------------------------------------------------------------------------
__global__ void wsum_kernel(const float* __restrict__ W) {
    int id = blockIdx.x * blockDim.x + threadIdx.x;
    if (id >= RR * CC * II) return;
    int rc = id / II, i = id - rc * II;
    int r = rc / CC, c = rc - r * CC;
    const float* p = W + rc * DD * II + i;
    float s = 0.f;
    #pragma unroll
    for (int d = 0; d < DD; d++) s += p[d * II];
    g_wsumT[(c * II + i) * RR + r] = s;
}

// ---------------------------------------------------------------------------
// t[c][b][r] = sum_i wsumT[c][i][r] * u[b,r,i]
// ---------------------------------------------------------------------------
__global__ __launch_bounds__(128) void t_kernel(const float* __restrict__ u) {
    const int r = blockIdx.x * 128 + threadIdx.x;
    const int b0 = blockIdx.y * BTB;

    float uu[BTB][II];
    #pragma unroll
    for (int bi = 0; bi < BTB; bi++) {
        const float4* up = (const float4*)(u + ((b0 + bi) * RR + r) * II);
        float4 a = up[0], b = up[1];
        uu[bi][0] = a.x; uu[bi][1] = a.y; uu[bi][2] = a.z; uu[bi][3] = a.w;
        uu[bi][4] = b.x; uu[bi][5] = b.y; uu[bi][6] = b.z; uu[bi][7] = b.w;
    }

    #pragma unroll
    for (int c = 0; c < CC; c++) {
        float ws[II];
        #pragma unroll
        for (int i = 0; i < II; i++) ws[i] = g_wsumT[(c * II + i) * RR + r];
        #pragma unroll
        for (int bi = 0; bi < BTB; bi++) {
            float s = 0.f;
            #pragma unroll
            for (int i = 0; i < II; i++) s += ws[i] * uu[bi][i];
            g_t[(c * BB + b0 + bi) * RR + r] = s;
        }
    }
}

// ---------------------------------------------------------------------------
// Tensor-core GEMM (legacy mma.sync m16n8k8 tf32):
// spart[kb][b][n] = sum_{r in chunk kb} c[r,n] * sum_i u[b,r,i] * W[r,n,i]
// Stage = 4 routes (K32); fragments staged in mma layout; reg-prefetch
// double buffering with ONE __syncthreads per stage.
// 8 warps: warp (mg = wid&3, nh = wid>>2) computes m16 x n80 (10 n-tiles).
// ---------------------------------------------------------------------------
__global__ __launch_bounds__(256, 1) void mma_gemm_kernel(
    const float* __restrict__ u, const float* __restrict__ W,
    int use_c, float cuni)
{
    extern __shared__ uint32_t sm[];
    uint32_t* As = sm;
    uint32_t* Bs = sm + A_WORDS;

    const int tid = threadIdx.x;
    const int lane = tid & 31, wid = tid >> 5;
    const int mg = wid & 3, nh = wid >> 2;
    const int bt = blockIdx.x, kb = blockIdx.y;
    const int b0 = bt * MT, r0 = kb * RCHUNK;

    float acc[10][4];
    #pragma unroll
    for (int nt = 0; nt < 10; nt++)
        #pragma unroll
        for (int q = 0; q < 4; q++) acc[nt][q] = 0.f;

    // ---- staging decomposition (stage-invariant) ----
    // A: one row per thread: (b = ab, route-in-stage = arr), 8 floats
    const int ab = tid >> 2, arr = tid & 3;
    const int amg = ab >> 4, ag = ab & 15;
    const int alo = ag >> 3;               // 0: a0/a2 rows, 1: a1/a3 rows
    const int albase = (ag & 7) * 4;
    const float* aup = u + ((b0 + ab) * RR + r0 + arr) * II;

    // B: up to 3 rows per thread: q = tid + 256j over 640 = 160n x 4rr
    int brr[3], bnh[3], bnt[3], bg[3], bwoff[3];
    bool bok[3];
    #pragma unroll
    for (int j = 0; j < 3; j++) {
        int q = tid + 256 * j;
        bok[j] = q < 640;
        int qq = bok[j] ? q : 0;
        brr[j] = qq / 160;
        int n = qq - brr[j] * 160;
        bnh[j] = n >= 80 ? 1 : 0;
        bnt[j] = (n - bnh[j] * 80) >> 3;
        bg[j]  = n & 7;
        bwoff[j] = (r0 + brr[j]) * NN + n;   // W row / g_c index
    }

    // prefetch registers
    float4 pa0, pa1;
    float4 pb0[3], pb1[3];
    float  pc[3];

    // prologue: prefetch stage 0
    {
        pa0 = *(const float4*)(aup);
        pa1 = *(const float4*)(aup + 4);
        #pragma unroll
        for (int j = 0; j < 3; j++) {
            if (bok[j]) {
                pc[j]  = use_c ? g_c[bwoff[j]] : cuni;
                pb0[j] = *(const float4*)(W + bwoff[j] * 8);
                pb1[j] = *(const float4*)(W + bwoff[j] * 8 + 4);
            }
        }
    }

    #pragma unroll 2
    for (int st = 0; st < NSTAGE; st++) {
        const int buf = st & 1;

        // ---- commit A: 4 STS.64 (pairs (a0,a2) or (a1,a3) per k-col) ----
        {
            float af[8] = {pa0.x, pa0.y, pa0.z, pa0.w, pa1.x, pa1.y, pa1.z, pa1.w};
            uint32_t* Ab = As + A_WORD(buf, amg, arr, 0, 0) + alo * 2;
            #pragma unroll
            for (int tp = 0; tp < 4; tp++) {
                uint2 v = make_uint2(f2tf32(af[tp]), f2tf32(af[tp + 4]));
                *(uint2*)&Ab[(albase + tp) * 4] = v;
            }
        }
        // ---- commit B: 2 STS.128 per row (word order i: 0,4,1,5 | 2,6,3,7) ----
        #pragma unroll
        for (int j = 0; j < 3; j++) {
            if (bok[j]) {
                float c = pc[j];
                uint32_t* Bb = Bs + B_BASE(buf, bnh[j], bnt[j], brr[j]) + bg[j] * 8;
                uint4 w0 = make_uint4(f2tf32(pb0[j].x * c), f2tf32(pb1[j].x * c),
                                      f2tf32(pb0[j].y * c), f2tf32(pb1[j].y * c));
                uint4 w1 = make_uint4(f2tf32(pb0[j].z * c), f2tf32(pb1[j].z * c),
                                      f2tf32(pb0[j].w * c), f2tf32(pb1[j].w * c));
                *(uint4*)&Bb[0] = w0;
                *(uint4*)&Bb[4] = w1;
            }
        }
        __syncthreads();   // buf visible; also guards next commit to other buf

        // ---- prefetch next stage ----
        if (st < NSTAGE - 1) {
            const float* ua = aup + (st + 1) * 32;      // +4 routes * 8 floats
            pa0 = *(const float4*)(ua);
            pa1 = *(const float4*)(ua + 4);
            #pragma unroll
            for (int j = 0; j < 3; j++) {
                if (bok[j]) {
                    int o = bwoff[j] + (st + 1) * 4 * NN;
                    pc[j]  = use_c ? g_c[o] : cuni;
                    pb0[j] = *(const float4*)(W + o * 8);
                    pb1[j] = *(const float4*)(W + o * 8 + 4);
                }
            }
        }

        // ---- compute: 4 k-tiles x 10 n-tiles of m16n8k8 ----
        #pragma unroll
        for (int kt = 0; kt < 4; kt++) {
            uint4 av = *(const uint4*)&As[A_WORD(buf, mg, kt, lane, 0)];
            // slots: x=a0, y=a2, z=a1, w=a3
            #pragma unroll
            for (int nt = 0; nt < 10; nt++) {
                uint2 bv = *(const uint2*)&Bs[B_BASE(buf, nh, nt, kt) + 2 * lane];
                asm volatile(
                    "mma.sync.aligned.m16n8k8.row.col.f32.tf32.tf32.f32 "
                    "{%0,%1,%2,%3}, {%4,%5,%6,%7}, {%8,%9}, {%0,%1,%2,%3};"
                    : "+f"(acc[nt][0]), "+f"(acc[nt][1]),
                      "+f"(acc[nt][2]), "+f"(acc[nt][3])
                    : "r"(av.x), "r"(av.z), "r"(av.y), "r"(av.w),
                      "r"(bv.x), "r"(bv.y));
            }
        }
    }

    // ---- epilogue: fragment -> spart (float2 stores) ----
    {
        const int g = lane >> 2, t = lane & 3;
        const int m = b0 + mg * 16 + g;
        #pragma unroll
        for (int nt = 0; nt < 10; nt++) {
            int n = nh * 80 + nt * 8 + 2 * t;
            *(float2*)&g_spart[(kb * BB + m) * NN + n] =
                make_float2(acc[nt][0], acc[nt][1]);
            *(float2*)&g_spart[(kb * BB + m + 8) * NN + n] =
                make_float2(acc[nt][2], acc[nt][3]);
        }
    }
}

// ---------------------------------------------------------------------------
// Reduce K-chunk partials (36), squash, write v (and final output).
// ---------------------------------------------------------------------------
__global__ __launch_bounds__(128) void reduce_squash_kernel(float* __restrict__ dout) {
    const int idx = blockIdx.x * 128 + threadIdx.x;   // over BB*NN = 40960
    const int stride = BB * NN;

    float s = 0.f;
    #pragma unroll
    for (int bat = 0; bat < NKB / 12; bat++) {
        float x[12];
        #pragma unroll
        for (int j = 0; j < 12; j++)
            x[j] = g_spart[(bat * 12 + j) * stride + idx];
        float a0 = 0.f, a1 = 0.f, a2 = 0.f, a3 = 0.f;
        #pragma unroll
        for (int j = 0; j < 12; j += 4) {
            a0 += x[j]; a1 += x[j + 1]; a2 += x[j + 2]; a3 += x[j + 3];
        }
        s += (a0 + a1) + (a2 + a3);
    }

    float sq = s * s;
    float o = sq / (1.f + sq) * s / (sqrtf(sq) + 1e-5f);
    g_v[idx] = o;
    dout[idx] = o;
}

// ---------------------------------------------------------------------------
// bT[c*16+d][r] += (1/B) sum_b t[c][b][r] * v[b, c*16+d]
// ---------------------------------------------------------------------------
__global__ __launch_bounds__(128) void update_kernel(int first) {
    __shared__ u64 v_s[BB][DD / 2];   // 16 KB
    const int c = blockIdx.y;
    const int r = blockIdx.x * 128 + threadIdx.x;

    #pragma unroll
    for (int k = 0; k < 8; k++) {
        int idx = threadIdx.x + 128 * k;
        int b = idx >> 2, q = idx & 3;
        const float4 v4 = *(const float4*)(g_v + b * NN + c * DD + q * 4);
        v_s[b][q * 2 + 0] = pack2(v4.x, v4.y);
        v_s[b][q * 2 + 1] = pack2(v4.z, v4.w);
    }
    __syncthreads();

    const u64 z = pack2(0.f, 0.f);
    u64 acc[8];
    #pragma unroll
    for (int j = 0; j < 8; j++) acc[j] = z;

    const float* tp = g_t + (c * BB) * RR + r;
    for (int b0 = 0; b0 < BB; b0 += 8) {
        float tv[8];
        #pragma unroll
        for (int q = 0; q < 8; q++) tv[q] = tp[(b0 + q) * RR];
        #pragma unroll
        for (int q = 0; q < 8; q++) {
            u64 t2 = pack2(tv[q], tv[q]);
            #pragma unroll
            for (int j = 0; j < 8; j++) fma2(acc[j], t2, v_s[b0 + q][j]);
        }
    }

    const float inv = 1.f / (float)BB;
    #pragma unroll
    for (int j = 0; j < 8; j++) {
        float x = lo2(acc[j]) * inv;
        float y = hi2(acc[j]) * inv;
        int o0 = (c * DD + 2 * j) * RR + r;
        int o1 = (c * DD + 2 * j + 1) * RR + r;
        if (!first) { x += g_bT[o0]; y += g_bT[o1]; }
        g_bT[o0] = x;
        g_bT[o1] = y;
    }
}

// ---------------------------------------------------------------------------
// c[r,n] = softmax over r of bT[n][r].  grid NN blocks, 128 threads.
// ---------------------------------------------------------------------------
__global__ __launch_bounds__(128) void softmax_kernel() {
    __shared__ float red[128];
    const int n = blockIdx.x;
    const int tid = threadIdx.x;
    const float* bp = g_bT + n * RR;

    float vals[9];
    #pragma unroll
    for (int j = 0; j < 9; j++) vals[j] = bp[tid + 128 * j];

    float m = vals[0];
    #pragma unroll
    for (int j = 1; j < 9; j++) m = fmaxf(m, vals[j]);
    red[tid] = m;
    __syncthreads();
    for (int s = 64; s > 0; s >>= 1) {
        if (tid < s) red[tid] = fmaxf(red[tid], red[tid + s]);
        __syncthreads();
    }
    m = red[0];
    __syncthreads();

    float e[9];
    float lsum = 0.f;
    #pragma unroll
    for (int j = 0; j < 9; j++) { e[j] = expf(vals[j] - m); lsum += e[j]; }
    red[tid] = lsum;
    __syncthreads();
    for (int s = 64; s > 0; s >>= 1) {
        if (tid < s) red[tid] += red[tid + s];
        __syncthreads();
    }
    float inv = 1.f / red[0];

    #pragma unroll
    for (int j = 0; j < 9; j++)
        g_c[(tid + 128 * j) * NN + n] = e[j] * inv;
}

// ---------------------------------------------------------------------------
extern "C" void kernel_launch(void* const* d_in, const int* in_sizes, int n_in,
                              void* d_out, int out_size) {
    const float* u = (const float*)d_in[0];   // (B, R, 8)
    const float* W = (const float*)d_in[1];   // (R, C, 16, 8)
    float* out = (float*)d_out;               // (B, C, 16)

    cudaFuncSetAttribute(mma_gemm_kernel,
                         cudaFuncAttributeMaxDynamicSharedMemorySize, SMEM_TOTAL);

    wsum_kernel<<<(RR * CC * II + 255) / 256, 256>>>(W);
    t_kernel<<<dim3(RR / 128, BB / BTB), 128>>>(u);

    // Iteration 0: c_ij uniform = 1/R
    mma_gemm_kernel<<<dim3(NBT, NKB), 256, SMEM_TOTAL>>>(u, W, 0, 1.0f / (float)RR);
    reduce_squash_kernel<<<320, 128>>>(out);
    update_kernel<<<dim3(RR / 128, CC), 128>>>(1);
    softmax_kernel<<<NN, 128>>>();

    // Iteration 1
    mma_gemm_kernel<<<dim3(NBT, NKB), 256, SMEM_TOTAL>>>(u, W, 1, 0.f);
    reduce_squash_kernel<<<320, 128>>>(out);
    update_kernel<<<dim3(RR / 128, CC), 128>>>(0);
    softmax_kernel<<<NN, 128>>>();

    // Iteration 2 (final v -> out)
    mma_gemm_kernel<<<dim3(NBT, NKB), 256, SMEM_TOTAL>>>(u, W, 1, 0.f);
    reduce_squash_kernel<<<320, 128>>>(out);
}